// round 3
// baseline (speedup 1.0000x reference)
#include <cuda_runtime.h>
#include <cuda_bf16.h>
#include <cstdint>

#define B_SZ 1024
#define S_SZ 256
#define D_SZ 512
#define E_SZ 16
#define O_SZ 512

#define BM 128
#define BN 256
#define BK 64
#define KCHUNKS (D_SZ / BK)
#define NTHREADS 512

// Feature gate: defined only when codegen targets sm_103a (arch-specific pass).
#if defined(__CUDA_ARCH__) && defined(__CUDA_ARCH_FEAT_SM103_ALL)
#define USE_TCGEN05 1
#else
#define USE_TCGEN05 0
#endif

// ---------------- scratch (device globals; no allocation allowed) ----------------
__device__ __align__(16) __nv_bfloat16 g_Whi[E_SZ * O_SZ * D_SZ];
__device__ __align__(16) __nv_bfloat16 g_Wlo[E_SZ * O_SZ * D_SZ];
__device__ int   g_idx[B_SZ];
__device__ float g_gate[B_SZ];

// ---------------- common helpers ----------------
__device__ __forceinline__ uint32_t smem_to_u32(const void* p) {
    uint32_t a;
    asm("{ .reg .u64 t; cvta.to.shared.u64 t, %1; cvt.u32.u64 %0, t; }" : "=r"(a) : "l"(p));
    return a;
}
#define SMEM_SWIZZLE_128B(o) ((o) ^ (((o) >> 3) & 0x70))

__device__ __forceinline__ uint32_t pack_bf16x2(__nv_bfloat16 a, __nv_bfloat16 b) {
    uint16_t au = __bfloat16_as_ushort(a);
    uint16_t bu = __bfloat16_as_ushort(b);
    return (uint32_t)au | ((uint32_t)bu << 16);
}

#define CP_ASYNC16(dst_u32, src_ptr) \
    asm volatile("cp.async.cg.shared.global [%0], [%1], 16;" :: "r"(dst_u32), "l"(src_ptr))
#define CP_ASYNC_COMMIT() asm volatile("cp.async.commit_group;" ::: "memory")
#define CP_ASYNC_WAIT_ALL() asm volatile("cp.async.wait_group 0;" ::: "memory")

// ---------------- SMEM layout (both paths) ----------------
// [0..64)      : tmem ptr / mbarriers (tcgen05 path only)
// [1024 .. 1024+2*98304) : two 96KB stages
//   within a stage: A_HI 16KB | A_LO 16KB | B_HI 32KB | B_LO 32KB
// [197632 .. 198656) : bias (256 floats)
#define SMEM_TMEM_PTR 0
#define SMEM_MBAR0    16
#define SMEM_MBAR1    24
#define STAGE0_OFF    1024
#define STAGE_STRIDE  98304
#define OFF_AHI       0
#define OFF_ALO       16384
#define OFF_BHI       32768
#define OFF_BLO       65536
#define SMEM_BIAS     (STAGE0_OFF + 2 * STAGE_STRIDE)        // 197632
#define SMEM_STAGEBUF STAGE0_OFF                              // epilogue staging reuse
#define SMEM_TOTAL    (SMEM_BIAS + 1024 + 128)                // 198784

#if USE_TCGEN05
// ---------------- tcgen05 PTX helpers (sm_103a pass only) ----------------
__device__ __forceinline__ uint32_t elect_one_pred() {
    uint32_t pred;
    asm volatile(
        "{\n\t.reg .pred p;\n\t"
        "elect.sync _|p, 0xFFFFFFFF;\n\t"
        "selp.b32 %0, 1, 0, p;\n\t}"
        : "=r"(pred));
    return pred;
}
static constexpr uint64_t SMEM_DESC_BASE_SW128 =
    (uint64_t(2)  << 61) | (uint64_t(1) << 46) | (uint64_t(64) << 32) | (uint64_t(1) << 16);
#define MAKE_SMEM_DESC(base_addr) \
    (SMEM_DESC_BASE_SW128 | ((uint64_t)((base_addr) >> 4) & 0x3FFF))

#define TCGEN05_ALLOC(smem_result_addr, nCols) \
    asm volatile("tcgen05.alloc.cta_group::1.sync.aligned.shared::cta.b32 [%0], %1;" \
        :: "r"((uint32_t)(smem_result_addr)), "r"((uint32_t)(nCols)) : "memory")
#define TCGEN05_DEALLOC(tmem_addr, nCols) \
    asm volatile("tcgen05.dealloc.cta_group::1.sync.aligned.b32 %0, %1;" \
        :: "r"(tmem_addr), "r"((uint32_t)(nCols)))
#define TCGEN05_RELINQUISH_ALLOC_PERMIT() \
    asm volatile("tcgen05.relinquish_alloc_permit.cta_group::1.sync.aligned;")
#define TCGEN05_COMMIT(mbar_smem_addr) \
    asm volatile("tcgen05.commit.cta_group::1.mbarrier::arrive::one.shared::cluster.b64 [%0];" \
        :: "r"((uint32_t)(mbar_smem_addr)) : "memory")
#define TCGEN05_FENCE_AFTER() \
    asm volatile("tcgen05.fence::after_thread_sync;" ::: "memory")
#define TCGEN05_WAIT_LD() \
    asm volatile("tcgen05.wait::ld.sync.aligned;" ::: "memory")
#define FENCE_PROXY_ASYNC_SHARED_CTA() \
    asm volatile("fence.proxy.async.shared::cta;" ::: "memory")
#define MBARRIER_INIT(mbar_smem_addr, count) \
    asm volatile("mbarrier.init.shared.b64 [%0], %1;" \
        :: "r"((uint32_t)(mbar_smem_addr)), "r"((uint32_t)(count)) : "memory")
#define MBARRIER_WAIT_PARITY(mbar_smem_addr, phase_parity) do { \
    uint32_t _mbar = (uint32_t)(mbar_smem_addr); \
    uint32_t _parity = (uint32_t)(phase_parity); \
    uint32_t _done; \
    asm volatile( \
        "{\n\t.reg .pred p;\n\t" \
        "mbarrier.try_wait.parity.acquire.cta.shared::cta.b64 p, [%1], %2;\n\t" \
        "selp.b32 %0, 1, 0, p;\n\t}" \
        : "=r"(_done) : "r"(_mbar), "r"(_parity) : "memory"); \
    if (!_done) { \
        asm volatile( \
            "{\n\t.reg .pred P1;\n\t" \
            "WAIT_LOOP_%=:\n\t" \
            "mbarrier.try_wait.parity.acquire.cta.shared::cta.b64 P1, [%0], %1, 0x989680;\n\t" \
            "@P1 bra.uni WAIT_DONE_%=;\n\t" \
            "bra.uni WAIT_LOOP_%=;\n\t" \
            "WAIT_DONE_%=:\n\t}" \
            :: "r"(_mbar), "r"(_parity) : "memory"); \
    } \
} while(0)
#define TCGEN05_LD_32X32B_X32(r, tmem_addr) \
    asm volatile( \
        "tcgen05.ld.sync.aligned.32x32b.x32.b32 " \
        "{%0, %1, %2, %3, %4, %5, %6, %7, " \
        " %8, %9, %10, %11, %12, %13, %14, %15, " \
        " %16, %17, %18, %19, %20, %21, %22, %23, " \
        " %24, %25, %26, %27, %28, %29, %30, %31}, [%32];" \
        : "=r"((r)[0]),  "=r"((r)[1]),  "=r"((r)[2]),  "=r"((r)[3]), \
          "=r"((r)[4]),  "=r"((r)[5]),  "=r"((r)[6]),  "=r"((r)[7]), \
          "=r"((r)[8]),  "=r"((r)[9]),  "=r"((r)[10]), "=r"((r)[11]), \
          "=r"((r)[12]), "=r"((r)[13]), "=r"((r)[14]), "=r"((r)[15]), \
          "=r"((r)[16]), "=r"((r)[17]), "=r"((r)[18]), "=r"((r)[19]), \
          "=r"((r)[20]), "=r"((r)[21]), "=r"((r)[22]), "=r"((r)[23]), \
          "=r"((r)[24]), "=r"((r)[25]), "=r"((r)[26]), "=r"((r)[27]), \
          "=r"((r)[28]), "=r"((r)[29]), "=r"((r)[30]), "=r"((r)[31]) \
        : "r"(tmem_addr))

__device__ __forceinline__ void mma_f16_ss_cg1(uint32_t d_tmem, uint64_t a_desc,
                                               uint64_t b_desc, uint32_t idesc, bool acc) {
    uint32_t en = acc ? 1u : 0u;
    asm volatile(
        "{\n\t.reg .pred p;\n\t"
        "setp.ne.u32 p, %5, 0;\n\t"
        "tcgen05.mma.cta_group::1.kind::f16 [%0], %1, %2, %3, {%4, %4, %4, %4}, p;\n\t}"
        :: "r"(d_tmem), "l"(a_desc), "l"(b_desc), "r"(idesc), "r"(0u), "r"(en)
        : "memory");
}
static constexpr uint32_t MMA_IDESC =
    (1u << 4) | (1u << 7) | (1u << 10) | ((BN / 8) << 17) | ((BM / 16) << 24);
#endif  // USE_TCGEN05

// ---------------- fallback helpers (legal on plain sm_103) ----------------
#define LDSM_X4(r, addr) \
    asm volatile("ldmatrix.sync.aligned.m8n8.x4.shared.b16 {%0,%1,%2,%3}, [%4];" \
        : "=r"((r)[0]), "=r"((r)[1]), "=r"((r)[2]), "=r"((r)[3]) : "r"(addr))

#define MMA_BF16(d, a, b0, b1) \
    asm volatile("mma.sync.aligned.m16n8k16.row.col.f32.bf16.bf16.f32 " \
        "{%0,%1,%2,%3}, {%4,%5,%6,%7}, {%8,%9}, {%0,%1,%2,%3};" \
        : "+f"((d)[0]), "+f"((d)[1]), "+f"((d)[2]), "+f"((d)[3]) \
        : "r"((a)[0]), "r"((a)[1]), "r"((a)[2]), "r"((a)[3]), "r"(b0), "r"(b1))

// ================= gating: mean -> linear -> softmax -> argmax =================
__global__ void __launch_bounds__(512)
gating_kernel(const float* __restrict__ x,
              const float* __restrict__ Wg,
              const float* __restrict__ bg) {
    int b = blockIdx.x;
    int tid = threadIdx.x;            // 512 threads
    __shared__ float4 part[4][128];
    __shared__ float xm[D_SZ];
    __shared__ float logits[E_SZ];

    int grp = tid >> 7;               // s-phase 0..3
    int dq  = tid & 127;              // float4 index within D

    const float4* xp = reinterpret_cast<const float4*>(x + (size_t)b * S_SZ * D_SZ)
                       + (size_t)grp * (D_SZ / 4) + dq;
    float4 a = make_float4(0.f, 0.f, 0.f, 0.f);
#pragma unroll 8
    for (int s = 0; s < S_SZ / 4; s++) {
        float4 v = xp[(size_t)s * D_SZ];    // 4-row stride = 4 * D/4 float4
        a.x += v.x; a.y += v.y; a.z += v.z; a.w += v.w;
    }
    part[grp][dq] = a;
    __syncthreads();

    if (tid < 128) {
        float4 p0 = part[0][tid], p1 = part[1][tid], p2 = part[2][tid], p3 = part[3][tid];
        const float inv = 1.0f / S_SZ;
        xm[tid * 4 + 0] = (p0.x + p1.x + p2.x + p3.x) * inv;
        xm[tid * 4 + 1] = (p0.y + p1.y + p2.y + p3.y) * inv;
        xm[tid * 4 + 2] = (p0.z + p1.z + p2.z + p3.z) * inv;
        xm[tid * 4 + 3] = (p0.w + p1.w + p2.w + p3.w) * inv;
    }
    __syncthreads();

    int wid = tid >> 5, lane = tid & 31;   // 16 warps -> 16 experts
    float p = 0.f;
    for (int d = lane; d < D_SZ; d += 32) p += xm[d] * Wg[d * E_SZ + wid];
#pragma unroll
    for (int o = 16; o; o >>= 1) p += __shfl_xor_sync(0xffffffffu, p, o);
    if (lane == 0) logits[wid] = p + bg[wid];
    __syncthreads();

    if (tid == 0) {
        float mx = logits[0]; int mi = 0;
#pragma unroll
        for (int e = 1; e < E_SZ; e++) if (logits[e] > mx) { mx = logits[e]; mi = e; }
        float den = 0.f;
#pragma unroll
        for (int e = 0; e < E_SZ; e++) den += expf(logits[e] - mx);
        g_idx[b]  = mi;
        g_gate[b] = 1.0f / den;
    }
}

// ========== convert We[E,D,O] fp32 -> g_Whi/g_Wlo[E,O,D] bf16 (K-major B operand) ==========
__global__ void convert_w_kernel(const float* __restrict__ We) {
    __shared__ float tile[32][33];
    int e  = blockIdx.z;
    int d0 = blockIdx.y * 32;
    int o0 = blockIdx.x * 32;
    int tx = threadIdx.x, ty = threadIdx.y;   // 32 x 8

    const float* src = We + ((size_t)e * D_SZ + d0) * O_SZ + o0;
#pragma unroll
    for (int k = 0; k < 4; k++)
        tile[ty + 8 * k][tx] = src[(size_t)(ty + 8 * k) * O_SZ + tx];
    __syncthreads();

    size_t dst = ((size_t)e * O_SZ + o0) * D_SZ + d0;
#pragma unroll
    for (int k = 0; k < 4; k++) {
        float v = tile[tx][ty + 8 * k];
        __nv_bfloat16 hi = __float2bfloat16(v);
        float r = v - __bfloat162float(hi);
        g_Whi[dst + (size_t)(ty + 8 * k) * D_SZ + tx] = hi;
        g_Wlo[dst + (size_t)(ty + 8 * k) * D_SZ + tx] = __float2bfloat16(r);
    }
}

#if !USE_TCGEN05
// fallback per-chunk compute: ldmatrix + 3x mma per (t, ntile)
__device__ __forceinline__ void fb_compute(uint32_t sA_hi, uint32_t sA_lo,
                                           uint32_t sB_hi, uint32_t sB_lo,
                                           int lane, int wm, int wn,
                                           float acc[2][8][4]) {
#pragma unroll
    for (int ks = 0; ks < 4; ks++) {
        uint32_t ah[2][4], al[2][4];
#pragma unroll
        for (int t = 0; t < 2; t++) {
            int row = wm * 32 + t * 16 + (lane & 15);
            int bc  = ks * 32 + ((lane >> 4) << 4);
            uint32_t sw = SMEM_SWIZZLE_128B((uint32_t)(row * 128 + bc));
            LDSM_X4(ah[t], sA_hi + sw);
            LDSM_X4(al[t], sA_lo + sw);
        }
#pragma unroll
        for (int half = 0; half < 2; half++) {
            uint32_t bh[2][4], bl[2][4];
#pragma unroll
            for (int q = 0; q < 2; q++) {
                int nbase = wn * 64 + half * 32 + q * 16;
                int row = nbase + (lane & 7) + ((lane >> 4) << 3);
                int bc  = ks * 32 + (((lane >> 3) & 1) << 4);
                uint32_t sw = SMEM_SWIZZLE_128B((uint32_t)(row * 128 + bc));
                LDSM_X4(bh[q], sB_hi + sw);
                LDSM_X4(bl[q], sB_lo + sw);
            }
#pragma unroll
            for (int t = 0; t < 2; t++) {
#pragma unroll
                for (int j = 0; j < 4; j++) {
                    int ntile = half * 4 + j;
                    uint32_t bh0 = bh[j >> 1][(j & 1) * 2];
                    uint32_t bh1 = bh[j >> 1][(j & 1) * 2 + 1];
                    uint32_t bl0 = bl[j >> 1][(j & 1) * 2];
                    uint32_t bl1 = bl[j >> 1][(j & 1) * 2 + 1];
                    MMA_BF16(acc[t][ntile], ah[t], bh0, bh1);
                    MMA_BF16(acc[t][ntile], ah[t], bl0, bl1);
                    MMA_BF16(acc[t][ntile], al[t], bh0, bh1);
                }
            }
        }
    }
}
#endif

// ================= main per-batch expert GEMM =================
__global__ void __launch_bounds__(NTHREADS, 1)
moe_gemm_kernel(const float* __restrict__ x,
                const float* __restrict__ be,
                float* __restrict__ out) {
    extern __shared__ char smem[];
    uint32_t smem_base = smem_to_u32(smem);
    int tid  = threadIdx.x;
    int wid  = tid >> 5;
    int lane = tid & 31;

    int bx = blockIdx.x;          // 4096 = B * 2(Mtiles) * 2(Ntiles)
    int b  = bx >> 2;
    int mt = (bx >> 1) & 1;
    int nt = bx & 1;
    int m0 = mt * BM;
    int n0 = nt * BN;

    int   e    = g_idx[b];
    float gate = g_gate[b];

    const float* xA = x + ((size_t)b * S_SZ + m0) * D_SZ;                 // [128, 512]
    const __nv_bfloat16* Bh = g_Whi + ((size_t)e * O_SZ + n0) * D_SZ;     // [256, 512]
    const __nv_bfloat16* Bl = g_Wlo + ((size_t)e * O_SZ + n0) * D_SZ;

    const uint32_t stg_u32[2] = { smem_base + STAGE0_OFF,
                                  smem_base + STAGE0_OFF + STAGE_STRIDE };
    char* const stg_ptr[2] = { smem + STAGE0_OFF, smem + STAGE0_OFF + STAGE_STRIDE };

    if (tid < BN)
        *(float*)(smem + SMEM_BIAS + tid * 4) = be[(size_t)e * O_SZ + n0 + tid];

#if USE_TCGEN05
    // ================== tcgen05 path (double-buffered, 2 mbarriers) ==================
    if (wid == 0) {
        TCGEN05_ALLOC(smem_base + SMEM_TMEM_PTR, 256);
        TCGEN05_RELINQUISH_ALLOC_PERMIT();
    }
    if (tid == 0) {
        MBARRIER_INIT(smem_base + SMEM_MBAR0, 1);
        MBARRIER_INIT(smem_base + SMEM_MBAR1, 1);
    }
    __syncthreads();

    uint32_t tmem_base;
    asm volatile("ld.shared.b32 %0, [%1];" : "=r"(tmem_base) : "r"(smem_base + SMEM_TMEM_PTR));

    uint64_t aHi[2], aLo[2], bHi[2], bLo[2];
#pragma unroll
    for (int s = 0; s < 2; s++) {
        aHi[s] = MAKE_SMEM_DESC(stg_u32[s] + OFF_AHI);
        aLo[s] = MAKE_SMEM_DESC(stg_u32[s] + OFF_ALO);
        bHi[s] = MAKE_SMEM_DESC(stg_u32[s] + OFF_BHI);
        bLo[s] = MAKE_SMEM_DESC(stg_u32[s] + OFF_BLO);
    }

    for (int c = 0; c < KCHUNKS; c++) {
        int cur = c & 1;
        if (c >= 2) {
            uint32_t mbar = smem_base + (cur ? SMEM_MBAR1 : SMEM_MBAR0);
            int par = ((c >> 1) - 1) & 1;
            MBARRIER_WAIT_PARITY(mbar, par);   // stage cur's previous MMA done
        }
        int k0 = c * BK;
        char* sp = stg_ptr[cur];
#pragma unroll
        for (int i = 0; i < 4; i++) {
            int idx4 = tid + i * NTHREADS;
            int r  = idx4 >> 4;
            int cq = idx4 & 15;
            float4 v = *(const float4*)(xA + (size_t)r * D_SZ + k0 + cq * 4);
            __nv_bfloat16 h0 = __float2bfloat16(v.x);
            __nv_bfloat16 h1 = __float2bfloat16(v.y);
            __nv_bfloat16 h2 = __float2bfloat16(v.z);
            __nv_bfloat16 h3 = __float2bfloat16(v.w);
            __nv_bfloat16 l0 = __float2bfloat16(v.x - __bfloat162float(h0));
            __nv_bfloat16 l1 = __float2bfloat16(v.y - __bfloat162float(h1));
            __nv_bfloat16 l2 = __float2bfloat16(v.z - __bfloat162float(h2));
            __nv_bfloat16 l3 = __float2bfloat16(v.w - __bfloat162float(h3));
            uint32_t sw = SMEM_SWIZZLE_128B((uint32_t)(r * 128 + cq * 8));
            *(uint2*)(sp + OFF_AHI + sw) = make_uint2(pack_bf16x2(h0, h1), pack_bf16x2(h2, h3));
            *(uint2*)(sp + OFF_ALO + sw) = make_uint2(pack_bf16x2(l0, l1), pack_bf16x2(l2, l3));
        }
#pragma unroll
        for (int i = 0; i < 4; i++) {
            int idx = tid + i * NTHREADS;
            int r  = idx >> 3;
            int cq = idx & 7;
            uint32_t sw = SMEM_SWIZZLE_128B((uint32_t)(r * 128 + cq * 16));
            *(uint4*)(sp + OFF_BHI + sw) = *(const uint4*)(Bh + (size_t)r * D_SZ + k0 + cq * 8);
            *(uint4*)(sp + OFF_BLO + sw) = *(const uint4*)(Bl + (size_t)r * D_SZ + k0 + cq * 8);
        }

        FENCE_PROXY_ASYNC_SHARED_CTA();
        __syncthreads();

        if (wid == 0) {
            if (elect_one_pred()) {
#pragma unroll
                for (int ks = 0; ks < 4; ks++) {
                    uint64_t ah = aHi[cur] + ks * 2;
                    uint64_t al = aLo[cur] + ks * 2;
                    uint64_t bh = bHi[cur] + ks * 2;
                    uint64_t bl = bLo[cur] + ks * 2;
                    bool first = (c == 0) && (ks == 0);
                    mma_f16_ss_cg1(tmem_base, ah, bh, MMA_IDESC, !first);
                    mma_f16_ss_cg1(tmem_base, ah, bl, MMA_IDESC, true);
                    mma_f16_ss_cg1(tmem_base, al, bh, MMA_IDESC, true);
                }
                uint32_t mbar = smem_base + (cur ? SMEM_MBAR1 : SMEM_MBAR0);
                TCGEN05_COMMIT(mbar);
            }
        }
        // no wait here: loads of chunk c+1 overlap MMA of chunk c
    }

    {   // final drain: both stages' last uses have parity ((KCHUNKS/2)-1)&1
        int par = ((KCHUNKS / 2) - 1) & 1;
        MBARRIER_WAIT_PARITY(smem_base + SMEM_MBAR0, par);
        MBARRIER_WAIT_PARITY(smem_base + SMEM_MBAR1, par);
    }
    TCGEN05_FENCE_AFTER();

    const float* biasp = (const float*)(smem + SMEM_BIAS);
    for (int cc = 0; cc < 8; cc++) {
        if (wid < 4) {
            uint32_t regs[32];
            TCGEN05_LD_32X32B_X32(regs, tmem_base + cc * 32);
            TCGEN05_WAIT_LD();
            int row = wid * 32 + lane;
            float* st = (float*)(smem + SMEM_STAGEBUF) + row * 33;
#pragma unroll
            for (int q = 0; q < 32; q++) st[q] = __uint_as_float(regs[q]);
        }
        __syncthreads();
#pragma unroll
        for (int i = 0; i < 2; i++) {
            int idx = tid + i * NTHREADS;
            int r = idx >> 3;
            int q = idx & 7;
            const float* st = (const float*)(smem + SMEM_STAGEBUF) + r * 33 + q * 4;
            int ncol = cc * 32 + q * 4;
            float4 v;
            v.x = gate * (st[0] + biasp[ncol + 0]);
            v.y = gate * (st[1] + biasp[ncol + 1]);
            v.z = gate * (st[2] + biasp[ncol + 2]);
            v.w = gate * (st[3] + biasp[ncol + 3]);
            *(float4*)(out + (((size_t)b * S_SZ + m0 + r) * O_SZ) + n0 + ncol) = v;
        }
        __syncthreads();
    }

    if (wid == 0) TCGEN05_DEALLOC(tmem_base, 256);

#else
    // ================== fallback path: double-buffered mma.sync bf16 ==================
    int wm = wid & 3;
    int wn = wid >> 2;

    float acc[2][8][4];
#pragma unroll
    for (int i = 0; i < 2; i++)
#pragma unroll
        for (int j = 0; j < 8; j++)
#pragma unroll
            for (int q = 0; q < 4; q++) acc[i][j][q] = 0.f;

    float4 av[4];

    // ---- prologue: stage 0 ----
    {
        const int k0 = 0;
#pragma unroll
        for (int i = 0; i < 4; i++) {
            int idx = tid + i * NTHREADS;
            int r  = idx >> 3;
            int cq = idx & 7;
            uint32_t sw = SMEM_SWIZZLE_128B((uint32_t)(r * 128 + cq * 16));
            CP_ASYNC16(stg_u32[0] + OFF_BHI + sw, Bh + (size_t)r * D_SZ + k0 + cq * 8);
            CP_ASYNC16(stg_u32[0] + OFF_BLO + sw, Bl + (size_t)r * D_SZ + k0 + cq * 8);
        }
        CP_ASYNC_COMMIT();
#pragma unroll
        for (int i = 0; i < 4; i++) {
            int idx4 = tid + i * NTHREADS;
            int r  = idx4 >> 4;
            int cq = idx4 & 15;
            av[i] = *(const float4*)(xA + (size_t)r * D_SZ + k0 + cq * 4);
        }
#pragma unroll
        for (int i = 0; i < 4; i++) {
            int idx4 = tid + i * NTHREADS;
            int r  = idx4 >> 4;
            int cq = idx4 & 15;
            __nv_bfloat16 h0 = __float2bfloat16(av[i].x);
            __nv_bfloat16 h1 = __float2bfloat16(av[i].y);
            __nv_bfloat16 h2 = __float2bfloat16(av[i].z);
            __nv_bfloat16 h3 = __float2bfloat16(av[i].w);
            __nv_bfloat16 l0 = __float2bfloat16(av[i].x - __bfloat162float(h0));
            __nv_bfloat16 l1 = __float2bfloat16(av[i].y - __bfloat162float(h1));
            __nv_bfloat16 l2 = __float2bfloat16(av[i].z - __bfloat162float(h2));
            __nv_bfloat16 l3 = __float2bfloat16(av[i].w - __bfloat162float(h3));
            uint32_t sw = SMEM_SWIZZLE_128B((uint32_t)(r * 128 + cq * 8));
            *(uint2*)(stg_ptr[0] + OFF_AHI + sw) = make_uint2(pack_bf16x2(h0, h1), pack_bf16x2(h2, h3));
            *(uint2*)(stg_ptr[0] + OFF_ALO + sw) = make_uint2(pack_bf16x2(l0, l1), pack_bf16x2(l2, l3));
        }
        CP_ASYNC_WAIT_ALL();
        __syncthreads();
    }

    for (int c = 0; c < KCHUNKS; c++) {
        int cur = c & 1;
        int nxt = cur ^ 1;
        bool more = (c + 1 < KCHUNKS);

        if (more) {
            int k0 = (c + 1) * BK;
#pragma unroll
            for (int i = 0; i < 4; i++) {
                int idx = tid + i * NTHREADS;
                int r  = idx >> 3;
                int cq = idx & 7;
                uint32_t sw = SMEM_SWIZZLE_128B((uint32_t)(r * 128 + cq * 16));
                CP_ASYNC16(stg_u32[nxt] + OFF_BHI + sw, Bh + (size_t)r * D_SZ + k0 + cq * 8);
                CP_ASYNC16(stg_u32[nxt] + OFF_BLO + sw, Bl + (size_t)r * D_SZ + k0 + cq * 8);
            }
            CP_ASYNC_COMMIT();
#pragma unroll
            for (int i = 0; i < 4; i++) {
                int idx4 = tid + i * NTHREADS;
                int r  = idx4 >> 4;
                int cq = idx4 & 15;
                av[i] = *(const float4*)(xA + (size_t)r * D_SZ + k0 + cq * 4);
            }
        }

        fb_compute(stg_u32[cur] + OFF_AHI, stg_u32[cur] + OFF_ALO,
                   stg_u32[cur] + OFF_BHI, stg_u32[cur] + OFF_BLO,
                   lane, wm, wn, acc);

        if (more) {
#pragma unroll
            for (int i = 0; i < 4; i++) {
                int idx4 = tid + i * NTHREADS;
                int r  = idx4 >> 4;
                int cq = idx4 & 15;
                __nv_bfloat16 h0 = __float2bfloat16(av[i].x);
                __nv_bfloat16 h1 = __float2bfloat16(av[i].y);
                __nv_bfloat16 h2 = __float2bfloat16(av[i].z);
                __nv_bfloat16 h3 = __float2bfloat16(av[i].w);
                __nv_bfloat16 l0 = __float2bfloat16(av[i].x - __bfloat162float(h0));
                __nv_bfloat16 l1 = __float2bfloat16(av[i].y - __bfloat162float(h1));
                __nv_bfloat16 l2 = __float2bfloat16(av[i].z - __bfloat162float(h2));
                __nv_bfloat16 l3 = __float2bfloat16(av[i].w - __bfloat162float(h3));
                uint32_t sw = SMEM_SWIZZLE_128B((uint32_t)(r * 128 + cq * 8));
                *(uint2*)(stg_ptr[nxt] + OFF_AHI + sw) = make_uint2(pack_bf16x2(h0, h1), pack_bf16x2(h2, h3));
                *(uint2*)(stg_ptr[nxt] + OFF_ALO + sw) = make_uint2(pack_bf16x2(l0, l1), pack_bf16x2(l2, l3));
            }
            CP_ASYNC_WAIT_ALL();
        }
        __syncthreads();
    }

    // epilogue: direct register stores with gate*(acc+bias)
    const float* biasp = (const float*)(smem + SMEM_BIAS);
#pragma unroll
    for (int t = 0; t < 2; t++) {
#pragma unroll
        for (int j = 0; j < 8; j++) {
            int col = wn * 64 + j * 8 + (lane & 3) * 2;
            int r0  = m0 + wm * 32 + t * 16 + (lane >> 2);
            float b0v = biasp[col], b1v = biasp[col + 1];
            float2 v0, v1;
            v0.x = gate * (acc[t][j][0] + b0v);
            v0.y = gate * (acc[t][j][1] + b1v);
            v1.x = gate * (acc[t][j][2] + b0v);
            v1.y = gate * (acc[t][j][3] + b1v);
            *(float2*)(out + ((size_t)b * S_SZ + r0) * O_SZ + n0 + col)       = v0;
            *(float2*)(out + ((size_t)b * S_SZ + r0 + 8) * O_SZ + n0 + col)   = v1;
        }
    }
#endif
}

// ================= launch =================
extern "C" void kernel_launch(void* const* d_in, const int* in_sizes, int n_in,
                              void* d_out, int out_size) {
    const float* x  = (const float*)d_in[0];
    const float* Wg = (const float*)d_in[1];
    const float* bg = (const float*)d_in[2];
    const float* We = (const float*)d_in[3];
    const float* be = (const float*)d_in[4];
    float* out = (float*)d_out;

    gating_kernel<<<B_SZ, 512>>>(x, Wg, bg);

    dim3 cgrid(O_SZ / 32, D_SZ / 32, E_SZ);
    convert_w_kernel<<<cgrid, dim3(32, 8)>>>(We);

    cudaFuncSetAttribute(moe_gemm_kernel,
                         cudaFuncAttributeMaxDynamicSharedMemorySize, SMEM_TOTAL);
    moe_gemm_kernel<<<B_SZ * 4, NTHREADS, SMEM_TOTAL>>>(x, be, out);
}

// round 4
// speedup vs baseline: 1.2985x; 1.2985x over previous
#include <cuda_runtime.h>
#include <cuda_bf16.h>
#include <cstdint>

#define B_SZ 1024
#define S_SZ 256
#define D_SZ 512
#define E_SZ 16
#define O_SZ 512

#define BM 128
#define BN 256
#define BK 64
#define KCHUNKS (D_SZ / BK)
#define NTHREADS 512

// Feature gate: defined only when codegen targets sm_103a (arch-specific pass).
#if defined(__CUDA_ARCH__) && defined(__CUDA_ARCH_FEAT_SM103_ALL)
#define USE_TCGEN05 1
#else
#define USE_TCGEN05 0
#endif

// ---------------- scratch (device globals; no allocation allowed) ----------------
__device__ __align__(16) __nv_bfloat16 g_Whi[E_SZ * O_SZ * D_SZ];
__device__ __align__(16) __nv_bfloat16 g_Wlo[E_SZ * O_SZ * D_SZ];
__device__ int   g_idx[B_SZ];
__device__ float g_gate[B_SZ];

// ---------------- common helpers ----------------
__device__ __forceinline__ uint32_t smem_to_u32(const void* p) {
    uint32_t a;
    asm("{ .reg .u64 t; cvta.to.shared.u64 t, %1; cvt.u32.u64 %0, t; }" : "=r"(a) : "l"(p));
    return a;
}
#define SMEM_SWIZZLE_128B(o) ((o) ^ (((o) >> 3) & 0x70))

__device__ __forceinline__ uint32_t pack_bf16x2(__nv_bfloat16 a, __nv_bfloat16 b) {
    uint16_t au = __bfloat16_as_ushort(a);
    uint16_t bu = __bfloat16_as_ushort(b);
    return (uint32_t)au | ((uint32_t)bu << 16);
}

#define CP_ASYNC16(dst_u32, src_ptr) \
    asm volatile("cp.async.cg.shared.global [%0], [%1], 16;" :: "r"(dst_u32), "l"(src_ptr))
#define CP_ASYNC_COMMIT() asm volatile("cp.async.commit_group;" ::: "memory")
#define CP_ASYNC_WAIT_ALL() asm volatile("cp.async.wait_group 0;" ::: "memory")

// ---------------- SMEM layout (both paths) ----------------
// [0..16)   tmem ptr
// [16..80)  mbarriers: full0, full1, empty0, empty1 (8B each)
// [1024 .. 1024+2*98304) : two 96KB stages
//   within a stage: A_HI 16KB | A_LO 16KB | B_HI 32KB | B_LO 32KB
// [197632 .. ) bias (256 floats)
#define SMEM_TMEM_PTR 0
#define SMEM_FULL0    16
#define SMEM_FULL1    24
#define SMEM_EMPTY0   32
#define SMEM_EMPTY1   40
#define STAGE0_OFF    1024
#define STAGE_STRIDE  98304
#define OFF_AHI       0
#define OFF_ALO       16384
#define OFF_BHI       32768
#define OFF_BLO       65536
#define SMEM_BIAS     (STAGE0_OFF + 2 * STAGE_STRIDE)        // 197632
#define SMEM_TOTAL    (SMEM_BIAS + 1024 + 128)               // 198784

#if USE_TCGEN05
// ---------------- tcgen05 PTX helpers (sm_103a pass only) ----------------
__device__ __forceinline__ uint32_t elect_one_pred() {
    uint32_t pred;
    asm volatile(
        "{\n\t.reg .pred p;\n\t"
        "elect.sync _|p, 0xFFFFFFFF;\n\t"
        "selp.b32 %0, 1, 0, p;\n\t}"
        : "=r"(pred));
    return pred;
}
static constexpr uint64_t SMEM_DESC_BASE_SW128 =
    (uint64_t(2)  << 61) | (uint64_t(1) << 46) | (uint64_t(64) << 32) | (uint64_t(1) << 16);
#define MAKE_SMEM_DESC(base_addr) \
    (SMEM_DESC_BASE_SW128 | ((uint64_t)((base_addr) >> 4) & 0x3FFF))

#define TCGEN05_ALLOC(smem_result_addr, nCols) \
    asm volatile("tcgen05.alloc.cta_group::1.sync.aligned.shared::cta.b32 [%0], %1;" \
        :: "r"((uint32_t)(smem_result_addr)), "r"((uint32_t)(nCols)) : "memory")
#define TCGEN05_DEALLOC(tmem_addr, nCols) \
    asm volatile("tcgen05.dealloc.cta_group::1.sync.aligned.b32 %0, %1;" \
        :: "r"(tmem_addr), "r"((uint32_t)(nCols)))
#define TCGEN05_RELINQUISH_ALLOC_PERMIT() \
    asm volatile("tcgen05.relinquish_alloc_permit.cta_group::1.sync.aligned;")
#define TCGEN05_COMMIT(mbar_smem_addr) \
    asm volatile("tcgen05.commit.cta_group::1.mbarrier::arrive::one.shared::cluster.b64 [%0];" \
        :: "r"((uint32_t)(mbar_smem_addr)) : "memory")
#define TCGEN05_FENCE_AFTER() \
    asm volatile("tcgen05.fence::after_thread_sync;" ::: "memory")
#define TCGEN05_WAIT_LD() \
    asm volatile("tcgen05.wait::ld.sync.aligned;" ::: "memory")
#define FENCE_PROXY_ASYNC_SHARED_CTA() \
    asm volatile("fence.proxy.async.shared::cta;" ::: "memory")
#define MBARRIER_INIT(mbar_smem_addr, count) \
    asm volatile("mbarrier.init.shared.b64 [%0], %1;" \
        :: "r"((uint32_t)(mbar_smem_addr)), "r"((uint32_t)(count)) : "memory")
#define MBARRIER_ARRIVE(mbar_smem_addr) \
    asm volatile("mbarrier.arrive.shared.b64 _, [%0];" \
        :: "r"((uint32_t)(mbar_smem_addr)) : "memory")
#define MBARRIER_WAIT_PARITY(mbar_smem_addr, phase_parity) do { \
    uint32_t _mbar = (uint32_t)(mbar_smem_addr); \
    uint32_t _parity = (uint32_t)(phase_parity); \
    uint32_t _done; \
    asm volatile( \
        "{\n\t.reg .pred p;\n\t" \
        "mbarrier.try_wait.parity.acquire.cta.shared::cta.b64 p, [%1], %2;\n\t" \
        "selp.b32 %0, 1, 0, p;\n\t}" \
        : "=r"(_done) : "r"(_mbar), "r"(_parity) : "memory"); \
    if (!_done) { \
        asm volatile( \
            "{\n\t.reg .pred P1;\n\t" \
            "WAIT_LOOP_%=:\n\t" \
            "mbarrier.try_wait.parity.acquire.cta.shared::cta.b64 P1, [%0], %1, 0x989680;\n\t" \
            "@P1 bra.uni WAIT_DONE_%=;\n\t" \
            "bra.uni WAIT_LOOP_%=;\n\t" \
            "WAIT_DONE_%=:\n\t}" \
            :: "r"(_mbar), "r"(_parity) : "memory"); \
    } \
} while(0)
#define TCGEN05_LD_32X32B_X32(r, tmem_addr) \
    asm volatile( \
        "tcgen05.ld.sync.aligned.32x32b.x32.b32 " \
        "{%0, %1, %2, %3, %4, %5, %6, %7, " \
        " %8, %9, %10, %11, %12, %13, %14, %15, " \
        " %16, %17, %18, %19, %20, %21, %22, %23, " \
        " %24, %25, %26, %27, %28, %29, %30, %31}, [%32];" \
        : "=r"((r)[0]),  "=r"((r)[1]),  "=r"((r)[2]),  "=r"((r)[3]), \
          "=r"((r)[4]),  "=r"((r)[5]),  "=r"((r)[6]),  "=r"((r)[7]), \
          "=r"((r)[8]),  "=r"((r)[9]),  "=r"((r)[10]), "=r"((r)[11]), \
          "=r"((r)[12]), "=r"((r)[13]), "=r"((r)[14]), "=r"((r)[15]), \
          "=r"((r)[16]), "=r"((r)[17]), "=r"((r)[18]), "=r"((r)[19]), \
          "=r"((r)[20]), "=r"((r)[21]), "=r"((r)[22]), "=r"((r)[23]), \
          "=r"((r)[24]), "=r"((r)[25]), "=r"((r)[26]), "=r"((r)[27]), \
          "=r"((r)[28]), "=r"((r)[29]), "=r"((r)[30]), "=r"((r)[31]) \
        : "r"(tmem_addr))

__device__ __forceinline__ void mma_f16_ss_cg1(uint32_t d_tmem, uint64_t a_desc,
                                               uint64_t b_desc, uint32_t idesc, bool acc) {
    uint32_t en = acc ? 1u : 0u;
    asm volatile(
        "{\n\t.reg .pred p;\n\t"
        "setp.ne.u32 p, %5, 0;\n\t"
        "tcgen05.mma.cta_group::1.kind::f16 [%0], %1, %2, %3, {%4, %4, %4, %4}, p;\n\t}"
        :: "r"(d_tmem), "l"(a_desc), "l"(b_desc), "r"(idesc), "r"(0u), "r"(en)
        : "memory");
}
static constexpr uint32_t MMA_IDESC =
    (1u << 4) | (1u << 7) | (1u << 10) | ((BN / 8) << 17) | ((BM / 16) << 24);
#endif  // USE_TCGEN05

// ---------------- fallback helpers (legal on plain sm_103) ----------------
#define LDSM_X4(r, addr) \
    asm volatile("ldmatrix.sync.aligned.m8n8.x4.shared.b16 {%0,%1,%2,%3}, [%4];" \
        : "=r"((r)[0]), "=r"((r)[1]), "=r"((r)[2]), "=r"((r)[3]) : "r"(addr))

#define MMA_BF16(d, a, b0, b1) \
    asm volatile("mma.sync.aligned.m16n8k16.row.col.f32.bf16.bf16.f32 " \
        "{%0,%1,%2,%3}, {%4,%5,%6,%7}, {%8,%9}, {%0,%1,%2,%3};" \
        : "+f"((d)[0]), "+f"((d)[1]), "+f"((d)[2]), "+f"((d)[3]) \
        : "r"((a)[0]), "r"((a)[1]), "r"((a)[2]), "r"((a)[3]), "r"(b0), "r"(b1))

// ================= gating: mean -> linear -> softmax -> argmax =================
__global__ void __launch_bounds__(512)
gating_kernel(const float* __restrict__ x,
              const float* __restrict__ Wg,
              const float* __restrict__ bg) {
    int b = blockIdx.x;
    int tid = threadIdx.x;            // 512 threads
    __shared__ float4 part[4][128];
    __shared__ float xm[D_SZ];
    __shared__ float logits[E_SZ];

    int grp = tid >> 7;               // s-phase 0..3
    int dq  = tid & 127;              // float4 index within D

    const float4* xp = reinterpret_cast<const float4*>(x + (size_t)b * S_SZ * D_SZ)
                       + (size_t)grp * (D_SZ / 4) + dq;
    float4 a = make_float4(0.f, 0.f, 0.f, 0.f);
#pragma unroll 16
    for (int s = 0; s < S_SZ / 4; s++) {
        float4 v = xp[(size_t)s * D_SZ];    // 4-row stride = 4 * D/4 float4
        a.x += v.x; a.y += v.y; a.z += v.z; a.w += v.w;
    }
    part[grp][dq] = a;
    __syncthreads();

    if (tid < 128) {
        float4 p0 = part[0][tid], p1 = part[1][tid], p2 = part[2][tid], p3 = part[3][tid];
        const float inv = 1.0f / S_SZ;
        xm[tid * 4 + 0] = (p0.x + p1.x + p2.x + p3.x) * inv;
        xm[tid * 4 + 1] = (p0.y + p1.y + p2.y + p3.y) * inv;
        xm[tid * 4 + 2] = (p0.z + p1.z + p2.z + p3.z) * inv;
        xm[tid * 4 + 3] = (p0.w + p1.w + p2.w + p3.w) * inv;
    }
    __syncthreads();

    int wid = tid >> 5, lane = tid & 31;   // 16 warps -> 16 experts
    float p = 0.f;
    for (int d = lane; d < D_SZ; d += 32) p += xm[d] * Wg[d * E_SZ + wid];
#pragma unroll
    for (int o = 16; o; o >>= 1) p += __shfl_xor_sync(0xffffffffu, p, o);
    if (lane == 0) logits[wid] = p + bg[wid];
    __syncthreads();

    if (tid == 0) {
        float mx = logits[0]; int mi = 0;
#pragma unroll
        for (int e = 1; e < E_SZ; e++) if (logits[e] > mx) { mx = logits[e]; mi = e; }
        float den = 0.f;
#pragma unroll
        for (int e = 0; e < E_SZ; e++) den += expf(logits[e] - mx);
        g_idx[b]  = mi;
        g_gate[b] = 1.0f / den;
    }
}

// ========== convert We[E,D,O] fp32 -> g_Whi/g_Wlo[E,O,D] bf16 (K-major B operand) ==========
__global__ void convert_w_kernel(const float* __restrict__ We) {
    __shared__ float tile[32][33];
    int e  = blockIdx.z;
    int d0 = blockIdx.y * 32;
    int o0 = blockIdx.x * 32;
    int tx = threadIdx.x, ty = threadIdx.y;   // 32 x 8

    const float* src = We + ((size_t)e * D_SZ + d0) * O_SZ + o0;
#pragma unroll
    for (int k = 0; k < 4; k++)
        tile[ty + 8 * k][tx] = src[(size_t)(ty + 8 * k) * O_SZ + tx];
    __syncthreads();

    size_t dst = ((size_t)e * O_SZ + o0) * D_SZ + d0;
#pragma unroll
    for (int k = 0; k < 4; k++) {
        float v = tile[tx][ty + 8 * k];
        __nv_bfloat16 hi = __float2bfloat16(v);
        float r = v - __bfloat162float(hi);
        g_Whi[dst + (size_t)(ty + 8 * k) * D_SZ + tx] = hi;
        g_Wlo[dst + (size_t)(ty + 8 * k) * D_SZ + tx] = __float2bfloat16(r);
    }
}

#if !USE_TCGEN05
// fallback per-chunk compute: ldmatrix + 3x mma per (t, ntile)
__device__ __forceinline__ void fb_compute(uint32_t sA_hi, uint32_t sA_lo,
                                           uint32_t sB_hi, uint32_t sB_lo,
                                           int lane, int wm, int wn,
                                           float acc[2][8][4]) {
#pragma unroll
    for (int ks = 0; ks < 4; ks++) {
        uint32_t ah[2][4], al[2][4];
#pragma unroll
        for (int t = 0; t < 2; t++) {
            int row = wm * 32 + t * 16 + (lane & 15);
            int bc  = ks * 32 + ((lane >> 4) << 4);
            uint32_t sw = SMEM_SWIZZLE_128B((uint32_t)(row * 128 + bc));
            LDSM_X4(ah[t], sA_hi + sw);
            LDSM_X4(al[t], sA_lo + sw);
        }
#pragma unroll
        for (int half = 0; half < 2; half++) {
            uint32_t bh[2][4], bl[2][4];
#pragma unroll
            for (int q = 0; q < 2; q++) {
                int nbase = wn * 64 + half * 32 + q * 16;
                int row = nbase + (lane & 7) + ((lane >> 4) << 3);
                int bc  = ks * 32 + (((lane >> 3) & 1) << 4);
                uint32_t sw = SMEM_SWIZZLE_128B((uint32_t)(row * 128 + bc));
                LDSM_X4(bh[q], sB_hi + sw);
                LDSM_X4(bl[q], sB_lo + sw);
            }
#pragma unroll
            for (int t = 0; t < 2; t++) {
#pragma unroll
                for (int j = 0; j < 4; j++) {
                    int ntile = half * 4 + j;
                    uint32_t bh0 = bh[j >> 1][(j & 1) * 2];
                    uint32_t bh1 = bh[j >> 1][(j & 1) * 2 + 1];
                    uint32_t bl0 = bl[j >> 1][(j & 1) * 2];
                    uint32_t bl1 = bl[j >> 1][(j & 1) * 2 + 1];
                    MMA_BF16(acc[t][ntile], ah[t], bh0, bh1);
                    MMA_BF16(acc[t][ntile], ah[t], bl0, bl1);
                    MMA_BF16(acc[t][ntile], al[t], bh0, bh1);
                }
            }
        }
    }
}
#endif

// ================= main per-batch expert GEMM =================
__global__ void __launch_bounds__(NTHREADS, 1)
moe_gemm_kernel(const float* __restrict__ x,
                const float* __restrict__ be,
                float* __restrict__ out) {
    extern __shared__ char smem[];
    uint32_t smem_base = smem_to_u32(smem);
    int tid  = threadIdx.x;
    int wid  = tid >> 5;
    int lane = tid & 31;

    int bx = blockIdx.x;          // 4096 = B * 2(Mtiles) * 2(Ntiles)
    int b  = bx >> 2;
    int mt = (bx >> 1) & 1;
    int nt = bx & 1;
    int m0 = mt * BM;
    int n0 = nt * BN;

    int   e    = g_idx[b];
    float gate = g_gate[b];

    const float* xA = x + ((size_t)b * S_SZ + m0) * D_SZ;                 // [128, 512]
    const __nv_bfloat16* Bh = g_Whi + ((size_t)e * O_SZ + n0) * D_SZ;     // [256, 512]
    const __nv_bfloat16* Bl = g_Wlo + ((size_t)e * O_SZ + n0) * D_SZ;

    const uint32_t stg_u32[2] = { smem_base + STAGE0_OFF,
                                  smem_base + STAGE0_OFF + STAGE_STRIDE };
    char* const stg_ptr[2] = { smem + STAGE0_OFF, smem + STAGE0_OFF + STAGE_STRIDE };

    if (tid < BN)
        *(float*)(smem + SMEM_BIAS + tid * 4) = be[(size_t)e * O_SZ + n0 + tid];

    // per-thread load coordinates (fixed across chunks)
    int ar[4], acq[4], br[4], bcq[4];
#pragma unroll
    for (int i = 0; i < 4; i++) {
        int idx4 = tid + i * NTHREADS;
        ar[i]  = idx4 >> 4;      // A row 0..127
        acq[i] = idx4 & 15;      // float4 within row
        br[i]  = idx4 >> 3;      // B row 0..255
        bcq[i] = idx4 & 7;       // 16B chunk within row
    }

#if USE_TCGEN05
    // ================== tcgen05 path: async producer/consumer pipeline ==================
    if (wid == 0) {
        TCGEN05_ALLOC(smem_base + SMEM_TMEM_PTR, 256);
        TCGEN05_RELINQUISH_ALLOC_PERMIT();
    }
    if (tid == 0) {
        MBARRIER_INIT(smem_base + SMEM_FULL0, NTHREADS);
        MBARRIER_INIT(smem_base + SMEM_FULL1, NTHREADS);
        MBARRIER_INIT(smem_base + SMEM_EMPTY0, 1);
        MBARRIER_INIT(smem_base + SMEM_EMPTY1, 1);
    }
    __syncthreads();

    uint32_t tmem_base;
    asm volatile("ld.shared.b32 %0, [%1];" : "=r"(tmem_base) : "r"(smem_base + SMEM_TMEM_PTR));

    uint64_t aHi[2], aLo[2], bHi[2], bLo[2];
#pragma unroll
    for (int s = 0; s < 2; s++) {
        aHi[s] = MAKE_SMEM_DESC(stg_u32[s] + OFF_AHI);
        aLo[s] = MAKE_SMEM_DESC(stg_u32[s] + OFF_ALO);
        bHi[s] = MAKE_SMEM_DESC(stg_u32[s] + OFF_BHI);
        bLo[s] = MAKE_SMEM_DESC(stg_u32[s] + OFF_BLO);
    }

    // register prefetch of chunk 0
    float4 av[4];
    uint4  bhv[4], blv[4];
#pragma unroll
    for (int i = 0; i < 4; i++) {
        av[i]  = *(const float4*)(xA + (size_t)ar[i] * D_SZ + acq[i] * 4);
        bhv[i] = *(const uint4*)(Bh + (size_t)br[i] * D_SZ + bcq[i] * 8);
        blv[i] = *(const uint4*)(Bl + (size_t)br[i] * D_SZ + bcq[i] * 8);
    }

    for (int c = 0; c < KCHUNKS; c++) {
        int s = c & 1;
        int u = c >> 1;
        uint32_t full_mbar  = smem_base + (s ? SMEM_FULL1  : SMEM_FULL0);
        uint32_t empty_mbar = smem_base + (s ? SMEM_EMPTY1 : SMEM_EMPTY0);

        if (u >= 1) MBARRIER_WAIT_PARITY(empty_mbar, (u - 1) & 1);

        char* sp = stg_ptr[s];
#pragma unroll
        for (int i = 0; i < 4; i++) {
            __nv_bfloat16 h0 = __float2bfloat16(av[i].x);
            __nv_bfloat16 h1 = __float2bfloat16(av[i].y);
            __nv_bfloat16 h2 = __float2bfloat16(av[i].z);
            __nv_bfloat16 h3 = __float2bfloat16(av[i].w);
            __nv_bfloat16 l0 = __float2bfloat16(av[i].x - __bfloat162float(h0));
            __nv_bfloat16 l1 = __float2bfloat16(av[i].y - __bfloat162float(h1));
            __nv_bfloat16 l2 = __float2bfloat16(av[i].z - __bfloat162float(h2));
            __nv_bfloat16 l3 = __float2bfloat16(av[i].w - __bfloat162float(h3));
            uint32_t swa = SMEM_SWIZZLE_128B((uint32_t)(ar[i] * 128 + acq[i] * 8));
            *(uint2*)(sp + OFF_AHI + swa) = make_uint2(pack_bf16x2(h0, h1), pack_bf16x2(h2, h3));
            *(uint2*)(sp + OFF_ALO + swa) = make_uint2(pack_bf16x2(l0, l1), pack_bf16x2(l2, l3));
            uint32_t swb = SMEM_SWIZZLE_128B((uint32_t)(br[i] * 128 + bcq[i] * 16));
            *(uint4*)(sp + OFF_BHI + swb) = bhv[i];
            *(uint4*)(sp + OFF_BLO + swb) = blv[i];
        }
        FENCE_PROXY_ASYNC_SHARED_CTA();
        MBARRIER_ARRIVE(full_mbar);

        // prefetch next chunk (overlaps MMA of this chunk)
        if (c + 1 < KCHUNKS) {
            int k0 = (c + 1) * BK;
#pragma unroll
            for (int i = 0; i < 4; i++) {
                av[i]  = *(const float4*)(xA + (size_t)ar[i] * D_SZ + k0 + acq[i] * 4);
                bhv[i] = *(const uint4*)(Bh + (size_t)br[i] * D_SZ + k0 + bcq[i] * 8);
                blv[i] = *(const uint4*)(Bl + (size_t)br[i] * D_SZ + k0 + bcq[i] * 8);
            }
        }

        if (wid == 0) {
            if (elect_one_pred()) {
                MBARRIER_WAIT_PARITY(full_mbar, u & 1);
#pragma unroll
                for (int ks = 0; ks < 4; ks++) {
                    uint64_t ah = aHi[s] + ks * 2;
                    uint64_t al = aLo[s] + ks * 2;
                    uint64_t bh = bHi[s] + ks * 2;
                    uint64_t bl = bLo[s] + ks * 2;
                    bool first = (c == 0) && (ks == 0);
                    mma_f16_ss_cg1(tmem_base, ah, bh, MMA_IDESC, !first);
                    mma_f16_ss_cg1(tmem_base, ah, bl, MMA_IDESC, true);
                    mma_f16_ss_cg1(tmem_base, al, bh, MMA_IDESC, true);
                }
                TCGEN05_COMMIT(empty_mbar);
            }
        }
    }

    {   // drain: last commit per stage is use #((KCHUNKS/2)-1)
        int par = ((KCHUNKS / 2) - 1) & 1;
        MBARRIER_WAIT_PARITY(smem_base + SMEM_EMPTY0, par);
        MBARRIER_WAIT_PARITY(smem_base + SMEM_EMPTY1, par);
    }
    __syncthreads();
    TCGEN05_FENCE_AFTER();

    // ---- direct-register epilogue: 16 warps, each 32 rows x 64 cols ----
    {
        const float* biasp = (const float*)(smem + SMEM_BIAS);
        int sub  = wid & 3;          // row group (subpartition)
        int part = wid >> 2;         // 64-col slice
        int row  = sub * 32 + lane;
        float* orow = out + (((size_t)b * S_SZ + m0 + row) * O_SZ) + n0;
#pragma unroll
        for (int cc = 0; cc < 2; cc++) {
            int col0 = part * 64 + cc * 32;
            uint32_t regs[32];
            TCGEN05_LD_32X32B_X32(regs, tmem_base + col0);
            TCGEN05_WAIT_LD();
#pragma unroll
            for (int q = 0; q < 8; q++) {
                float4 v;
                v.x = gate * (__uint_as_float(regs[q * 4 + 0]) + biasp[col0 + q * 4 + 0]);
                v.y = gate * (__uint_as_float(regs[q * 4 + 1]) + biasp[col0 + q * 4 + 1]);
                v.z = gate * (__uint_as_float(regs[q * 4 + 2]) + biasp[col0 + q * 4 + 2]);
                v.w = gate * (__uint_as_float(regs[q * 4 + 3]) + biasp[col0 + q * 4 + 3]);
                *(float4*)(orow + col0 + q * 4) = v;
            }
        }
    }
    __syncthreads();
    if (wid == 0) TCGEN05_DEALLOC(tmem_base, 256);

#else
    // ================== fallback path: double-buffered mma.sync bf16 ==================
    int wm = wid & 3;
    int wn = wid >> 2;

    float acc[2][8][4];
#pragma unroll
    for (int i = 0; i < 2; i++)
#pragma unroll
        for (int j = 0; j < 8; j++)
#pragma unroll
            for (int q = 0; q < 4; q++) acc[i][j][q] = 0.f;

    float4 av[4];

    // ---- prologue: stage 0 ----
    {
        const int k0 = 0;
#pragma unroll
        for (int i = 0; i < 4; i++) {
            uint32_t sw = SMEM_SWIZZLE_128B((uint32_t)(br[i] * 128 + bcq[i] * 16));
            CP_ASYNC16(stg_u32[0] + OFF_BHI + sw, Bh + (size_t)br[i] * D_SZ + k0 + bcq[i] * 8);
            CP_ASYNC16(stg_u32[0] + OFF_BLO + sw, Bl + (size_t)br[i] * D_SZ + k0 + bcq[i] * 8);
        }
        CP_ASYNC_COMMIT();
#pragma unroll
        for (int i = 0; i < 4; i++)
            av[i] = *(const float4*)(xA + (size_t)ar[i] * D_SZ + k0 + acq[i] * 4);
#pragma unroll
        for (int i = 0; i < 4; i++) {
            __nv_bfloat16 h0 = __float2bfloat16(av[i].x);
            __nv_bfloat16 h1 = __float2bfloat16(av[i].y);
            __nv_bfloat16 h2 = __float2bfloat16(av[i].z);
            __nv_bfloat16 h3 = __float2bfloat16(av[i].w);
            __nv_bfloat16 l0 = __float2bfloat16(av[i].x - __bfloat162float(h0));
            __nv_bfloat16 l1 = __float2bfloat16(av[i].y - __bfloat162float(h1));
            __nv_bfloat16 l2 = __float2bfloat16(av[i].z - __bfloat162float(h2));
            __nv_bfloat16 l3 = __float2bfloat16(av[i].w - __bfloat162float(h3));
            uint32_t sw = SMEM_SWIZZLE_128B((uint32_t)(ar[i] * 128 + acq[i] * 8));
            *(uint2*)(stg_ptr[0] + OFF_AHI + sw) = make_uint2(pack_bf16x2(h0, h1), pack_bf16x2(h2, h3));
            *(uint2*)(stg_ptr[0] + OFF_ALO + sw) = make_uint2(pack_bf16x2(l0, l1), pack_bf16x2(l2, l3));
        }
        CP_ASYNC_WAIT_ALL();
        __syncthreads();
    }

    for (int c = 0; c < KCHUNKS; c++) {
        int cur = c & 1;
        int nxt = cur ^ 1;
        bool more = (c + 1 < KCHUNKS);

        if (more) {
            int k0 = (c + 1) * BK;
#pragma unroll
            for (int i = 0; i < 4; i++) {
                uint32_t sw = SMEM_SWIZZLE_128B((uint32_t)(br[i] * 128 + bcq[i] * 16));
                CP_ASYNC16(stg_u32[nxt] + OFF_BHI + sw, Bh + (size_t)br[i] * D_SZ + k0 + bcq[i] * 8);
                CP_ASYNC16(stg_u32[nxt] + OFF_BLO + sw, Bl + (size_t)br[i] * D_SZ + k0 + bcq[i] * 8);
            }
            CP_ASYNC_COMMIT();
#pragma unroll
            for (int i = 0; i < 4; i++)
                av[i] = *(const float4*)(xA + (size_t)ar[i] * D_SZ + k0 + acq[i] * 4);
        }

        fb_compute(stg_u32[cur] + OFF_AHI, stg_u32[cur] + OFF_ALO,
                   stg_u32[cur] + OFF_BHI, stg_u32[cur] + OFF_BLO,
                   lane, wm, wn, acc);

        if (more) {
#pragma unroll
            for (int i = 0; i < 4; i++) {
                __nv_bfloat16 h0 = __float2bfloat16(av[i].x);
                __nv_bfloat16 h1 = __float2bfloat16(av[i].y);
                __nv_bfloat16 h2 = __float2bfloat16(av[i].z);
                __nv_bfloat16 h3 = __float2bfloat16(av[i].w);
                __nv_bfloat16 l0 = __float2bfloat16(av[i].x - __bfloat162float(h0));
                __nv_bfloat16 l1 = __float2bfloat16(av[i].y - __bfloat162float(h1));
                __nv_bfloat16 l2 = __float2bfloat16(av[i].z - __bfloat162float(h2));
                __nv_bfloat16 l3 = __float2bfloat16(av[i].w - __bfloat162float(h3));
                uint32_t sw = SMEM_SWIZZLE_128B((uint32_t)(ar[i] * 128 + acq[i] * 8));
                *(uint2*)(stg_ptr[nxt] + OFF_AHI + sw) = make_uint2(pack_bf16x2(h0, h1), pack_bf16x2(h2, h3));
                *(uint2*)(stg_ptr[nxt] + OFF_ALO + sw) = make_uint2(pack_bf16x2(l0, l1), pack_bf16x2(l2, l3));
            }
            CP_ASYNC_WAIT_ALL();
        }
        __syncthreads();
    }

    // epilogue: direct register stores with gate*(acc+bias)
    const float* biasp = (const float*)(smem + SMEM_BIAS);
#pragma unroll
    for (int t = 0; t < 2; t++) {
#pragma unroll
        for (int j = 0; j < 8; j++) {
            int col = wn * 64 + j * 8 + (lane & 3) * 2;
            int r0  = m0 + wm * 32 + t * 16 + (lane >> 2);
            float b0v = biasp[col], b1v = biasp[col + 1];
            float2 v0, v1;
            v0.x = gate * (acc[t][j][0] + b0v);
            v0.y = gate * (acc[t][j][1] + b1v);
            v1.x = gate * (acc[t][j][2] + b0v);
            v1.y = gate * (acc[t][j][3] + b1v);
            *(float2*)(out + ((size_t)b * S_SZ + r0) * O_SZ + n0 + col)       = v0;
            *(float2*)(out + ((size_t)b * S_SZ + r0 + 8) * O_SZ + n0 + col)   = v1;
        }
    }
#endif
}

// ================= launch =================
extern "C" void kernel_launch(void* const* d_in, const int* in_sizes, int n_in,
                              void* d_out, int out_size) {
    const float* x  = (const float*)d_in[0];
    const float* Wg = (const float*)d_in[1];
    const float* bg = (const float*)d_in[2];
    const float* We = (const float*)d_in[3];
    const float* be = (const float*)d_in[4];
    float* out = (float*)d_out;

    gating_kernel<<<B_SZ, 512>>>(x, Wg, bg);

    dim3 cgrid(O_SZ / 32, D_SZ / 32, E_SZ);
    convert_w_kernel<<<cgrid, dim3(32, 8)>>>(We);

    cudaFuncSetAttribute(moe_gemm_kernel,
                         cudaFuncAttributeMaxDynamicSharedMemorySize, SMEM_TOTAL);
    moe_gemm_kernel<<<B_SZ * 4, NTHREADS, SMEM_TOTAL>>>(x, be, out);
}